// round 16
// baseline (speedup 1.0000x reference)
#include <cuda_runtime.h>
#include <cuda_bf16.h>
#include <math.h>
#include <stdint.h>

// Problem constants
#define BB 64
#define TT 1024
#define DD 128
#define HH 256

// Scratch ping-pong buffers [B*T*H] fp32
__device__ float g_bufA[(size_t)BB * TT * HH];
__device__ float g_bufB[(size_t)BB * TT * HH];

// ---------------------------------------------------------------------------
// GEMM: C[M,N] = A[M,K] @ W[N,K]^T + b1[n] + b2[n]
// BM=128, BN=128, BK=16, 256 threads, TM=8, TN=8, packed f32x2 accumulators.
// (R4 version — proven)
// ---------------------------------------------------------------------------
__global__ __launch_bounds__(256)
void gemm_bias_kernel(const float* __restrict__ A,
                      const float* __restrict__ W,
                      const float* __restrict__ b1,
                      const float* __restrict__ b2,
                      float* __restrict__ C,
                      int M, int N, int K)
{
    __shared__ float As[16][128];
    __shared__ float Ws[16][128];

    const int m0 = blockIdx.y * 128;
    const int n0 = blockIdx.x * 128;
    const int tid = threadIdx.x;
    const int tr = tid >> 4;
    const int tc = tid & 15;

    uint64_t acc2[8][4];
#pragma unroll
    for (int i = 0; i < 8; i++)
#pragma unroll
        for (int l = 0; l < 4; l++) acc2[i][l] = 0ull;

    for (int k0 = 0; k0 < K; k0 += 16) {
#pragma unroll
        for (int it = 0; it < 2; it++) {
            int id  = tid + it * 256;
            int row = id >> 2;
            int c4  = (id & 3) << 2;
            float4 v = *(const float4*)&A[(size_t)(m0 + row) * K + k0 + c4];
            As[c4 + 0][row] = v.x;
            As[c4 + 1][row] = v.y;
            As[c4 + 2][row] = v.z;
            As[c4 + 3][row] = v.w;
        }
#pragma unroll
        for (int it = 0; it < 2; it++) {
            int id  = tid + it * 256;
            int row = id >> 2;
            int c4  = (id & 3) << 2;
            float4 v = *(const float4*)&W[(size_t)(n0 + row) * K + k0 + c4];
            Ws[c4 + 0][row] = v.x;
            Ws[c4 + 1][row] = v.y;
            Ws[c4 + 2][row] = v.z;
            Ws[c4 + 3][row] = v.w;
        }
        __syncthreads();

#pragma unroll
        for (int k = 0; k < 16; k++) {
            float a[8];
#pragma unroll
            for (int i = 0; i < 8; i++) a[i] = As[k][tr * 8 + i];
            uint64_t w2[4];
            const uint64_t* wp = (const uint64_t*)&Ws[k][tc * 8];
#pragma unroll
            for (int l = 0; l < 4; l++) w2[l] = wp[l];
#pragma unroll
            for (int i = 0; i < 8; i++) {
                uint64_t a2;
                asm("mov.b64 %0, {%1, %1};" : "=l"(a2) : "f"(a[i]));
#pragma unroll
                for (int l = 0; l < 4; l++)
                    asm("fma.rn.f32x2 %0, %1, %2, %0;"
                        : "+l"(acc2[i][l]) : "l"(a2), "l"(w2[l]));
            }
        }
        __syncthreads();
    }

    float bb[8];
#pragma unroll
    for (int l = 0; l < 8; l++) {
        int n = n0 + tc * 8 + l;
        bb[l] = b1[n] + b2[n];
    }
#pragma unroll
    for (int i = 0; i < 8; i++) {
        float r[8];
#pragma unroll
        for (int l = 0; l < 4; l++) {
            uint32_t lo, hi;
            asm("mov.b64 {%0, %1}, %2;" : "=r"(lo), "=r"(hi) : "l"(acc2[i][l]));
            r[2 * l]     = __uint_as_float(lo) + bb[2 * l];
            r[2 * l + 1] = __uint_as_float(hi) + bb[2 * l + 1];
        }
        float* crow = &C[(size_t)(m0 + tr * 8 + i) * N + n0 + tc * 8];
        *(float4*)crow       = make_float4(r[0], r[1], r[2], r[3]);
        *(float4*)(crow + 4) = make_float4(r[4], r[5], r[6], r[7]);
    }
}

// ---------------------------------------------------------------------------
// Recurrence: ONE CTA of 256 threads per batch element. No cluster, no mbar.
//   Thread j owns output row j: full 256-term dot per step.
//   Weights W_hh[j, :]: k-floats [0,128)   = 64 u64 in REGISTERS (R4-proven
//                                            no-spill footprint);
//                       k-floats [128,256) = 32 ulonglong2 in SMEM [32][256]
//                       (lane-stride-16B LDS.128, conflict-free).
//   h double-buffered in SMEM, read as broadcast LDS.128 (ulonglong2).
//   Per step: ONE __syncthreads.
//   Buffer-reuse proof: write hb[p^1](t) vs read hb[p^1](t+1) split by bar_t;
//   write hb[p](t+1) is after bar_t, read hb[p](t) before bar_t. OK.
// ---------------------------------------------------------------------------
#define NWREG 64   // u64 register weights (128 floats)
#define NSMW  32   // ulonglong2 smem weights per thread (128 floats)
#define REC_SMEM_BYTES (NSMW * 256 * 16 + 2 * 256 * 4)

template <bool TRANS>
__global__ __launch_bounds__(256, 1)
void rec_split_kernel(const float* __restrict__ xw,    // [B, T, H]
                      const float* __restrict__ Whh,   // [H, H]
                      float* __restrict__ out)
{
    extern __shared__ __align__(16) char smraw[];
    ulonglong2* Wsm = (ulonglong2*)smraw;                 // [32][256]
    float* hb = (float*)(smraw + NSMW * 256 * 16);        // [2][256]

    const int t0 = threadIdx.x;   // == output row j
    const int b  = blockIdx.x;

    // Load weights: 64 u64 (128 floats) to regs, 32 u128 (128 floats) to SMEM.
    uint64_t w[NWREG];
    {
        const uint64_t* wrow64 = (const uint64_t*)(Whh + (size_t)t0 * HH);
#pragma unroll
        for (int i = 0; i < NWREG; i++) w[i] = wrow64[i];
        const ulonglong2* wrow2 = (const ulonglong2*)wrow64;
#pragma unroll
        for (int i = 0; i < NSMW; i++) Wsm[i * 256 + t0] = wrow2[32 + i];
    }
    hb[t0] = 0.0f;
    hb[256 + t0] = 0.0f;
    __syncthreads();

    const float* xp = xw + (size_t)b * TT * HH + t0;
    float xin = xp[0];

    int p = 0;
    for (int t = 0; t < TT; ++t) {
        float xnext = (t + 1 < TT) ? xp[(size_t)(t + 1) * HH] : 0.0f;

        const ulonglong2* h2 = (const ulonglong2*)(hb + p * 256);  // 64 u64-pairs
        uint64_t a0 = 0ull, a1 = 0ull, a2 = 0ull, a3 = 0ull;

        // SMEM-weight part first (k-pair idx 32..63): LDS issues pipeline ahead.
#pragma unroll
        for (int i = 0; i < NSMW; i += 2) {
            ulonglong2 wv0 = Wsm[(i)     * 256 + t0];
            ulonglong2 wv1 = Wsm[(i + 1) * 256 + t0];
            ulonglong2 hv0 = h2[32 + i];
            ulonglong2 hv1 = h2[33 + i];
            asm("fma.rn.f32x2 %0, %1, %2, %0;" : "+l"(a0) : "l"(wv0.x), "l"(hv0.x));
            asm("fma.rn.f32x2 %0, %1, %2, %0;" : "+l"(a1) : "l"(wv0.y), "l"(hv0.y));
            asm("fma.rn.f32x2 %0, %1, %2, %0;" : "+l"(a2) : "l"(wv1.x), "l"(hv1.x));
            asm("fma.rn.f32x2 %0, %1, %2, %0;" : "+l"(a3) : "l"(wv1.y), "l"(hv1.y));
        }
        // Register-weight part (k-pair idx 0..31)
#pragma unroll
        for (int i = 0; i < 32; i += 2) {
            ulonglong2 v0 = h2[i];
            ulonglong2 v1 = h2[i + 1];
            asm("fma.rn.f32x2 %0, %1, %2, %0;" : "+l"(a0) : "l"(w[2*i + 0]), "l"(v0.x));
            asm("fma.rn.f32x2 %0, %1, %2, %0;" : "+l"(a1) : "l"(w[2*i + 1]), "l"(v0.y));
            asm("fma.rn.f32x2 %0, %1, %2, %0;" : "+l"(a2) : "l"(w[2*i + 2]), "l"(v1.x));
            asm("fma.rn.f32x2 %0, %1, %2, %0;" : "+l"(a3) : "l"(w[2*i + 3]), "l"(v1.y));
        }
        asm("add.rn.f32x2 %0, %0, %1;" : "+l"(a0) : "l"(a1));
        asm("add.rn.f32x2 %0, %0, %1;" : "+l"(a2) : "l"(a3));
        asm("add.rn.f32x2 %0, %0, %1;" : "+l"(a0) : "l"(a2));
        uint32_t lo, hi;
        asm("mov.b64 {%0, %1}, %2;" : "=r"(lo), "=r"(hi) : "l"(a0));
        float part = __uint_as_float(lo) + __uint_as_float(hi);

        float v = xin + part;
        float hval;
        asm("tanh.approx.f32 %0, %1;" : "=f"(hval) : "f"(v));
        hb[(p ^ 1) * 256 + t0] = hval;
        if (TRANS) out[((size_t)b * HH + t0) * TT + t] = hval;
        else       out[((size_t)b * TT + t) * HH + t0] = hval;
        xin = xnext;
        __syncthreads();
        p ^= 1;
    }
}

// ---------------------------------------------------------------------------
// Launch
// ---------------------------------------------------------------------------
extern "C" void kernel_launch(void* const* d_in, const int* in_sizes, int n_in,
                              void* d_out, int out_size)
{
    const float* x     = (const float*)d_in[0];
    const float* W_ih0 = (const float*)d_in[1];
    const float* W_hh0 = (const float*)d_in[2];
    const float* b_ih0 = (const float*)d_in[3];
    const float* b_hh0 = (const float*)d_in[4];
    const float* W_ih1 = (const float*)d_in[5];
    const float* W_hh1 = (const float*)d_in[6];
    const float* b_ih1 = (const float*)d_in[7];
    const float* b_hh1 = (const float*)d_in[8];
    float* out = (float*)d_out;

    float *bufA, *bufB;
    cudaGetSymbolAddress((void**)&bufA, g_bufA);
    cudaGetSymbolAddress((void**)&bufB, g_bufB);

    cudaFuncSetAttribute(rec_split_kernel<false>,
                         cudaFuncAttributeMaxDynamicSharedMemorySize, REC_SMEM_BYTES);
    cudaFuncSetAttribute(rec_split_kernel<true>,
                         cudaFuncAttributeMaxDynamicSharedMemorySize, REC_SMEM_BYTES);

    const int M = BB * TT;  // 65536

    // Layer 1 input projection: bufA = x @ W_ih0^T + (b_ih0 + b_hh0)
    gemm_bias_kernel<<<dim3(HH / 128, M / 128), 256>>>(
        x, W_ih0, b_ih0, b_hh0, bufA, M, HH, DD);

    // Layer 1 recurrence -> bufB = h1 [B,T,H]   (64 CTAs, 256 threads)
    rec_split_kernel<false><<<BB, 256, REC_SMEM_BYTES>>>(bufA, W_hh0, bufB);

    // Layer 2 input projection: bufA = h1 @ W_ih1^T + (b_ih1 + b_hh1)
    gemm_bias_kernel<<<dim3(HH / 128, M / 128), 256>>>(
        bufB, W_ih1, b_ih1, b_hh1, bufA, M, HH, HH);

    // Layer 2 recurrence -> out [B,H,T]
    rec_split_kernel<true><<<BB, 256, REC_SMEM_BYTES>>>(bufA, W_hh1, out);
}